// round 8
// baseline (speedup 1.0000x reference)
#include <cuda_runtime.h>
#include <cuda_bf16.h>
#include <cuda_fp16.h>
#include <math.h>

#define NN 50000
#define EE 800000
#define GG 256
#define LL 1000
#define HH 4
#define CC 32
#define FDIM 78
#define EDIM 128
#define VOC 26
#define KK 8
#define LOUTD 993
#define HC 128
#define XTF (CC*LOUTD)

typedef unsigned long long ull;

__device__ __forceinline__ void fma2(ull& acc, ull a, ull b) {
    asm("fma.rn.f32x2 %0, %1, %2, %0;" : "+l"(acc) : "l"(a), "l"(b));
}
__device__ __forceinline__ float2 unpack2(ull v) {
    float2 f; asm("mov.b64 {%0, %1}, %2;" : "=f"(f.x), "=f"(f.y) : "l"(v)); return f;
}

// ---------------- scratch ----------------
__device__ __align__(128) __half g_hh[NN*HC];    // fp16 h for gathers
__device__ __align__(128) float g_out[NN*HC];    // fp32 layer output (transform input)
__device__ __align__(16)  float g_asrc[NN*4];
__device__ __align__(16)  float g_adst[NN*4];
__device__ int   g_rowptr[NN+1];
__device__ int   g_cursor[NN];
__device__ int   g_csr[EE];
__device__ __align__(128) __half g_Bh[VOC*LL*HC];  // fp16 token->xt table
__device__ float g_wsum[VOC*KK*CC];
__device__ float g_cb2[HC];
__device__ __align__(16) float g_pooled[GG*HC];
__device__ float g_xtpre[GG*HC];
__device__ float g_xc[GG*256];
__device__ float g_h1[GG*1024];
__device__ float g_h2[GG*256];

// ---------------- init ----------------
__global__ void k_zero() {
    int i = blockIdx.x*256 + threadIdx.x;
    if (i < NN) g_cursor[i] = 0;
    if (i < GG*HC) { g_pooled[i] = 0.f; g_xtpre[i] = 0.f; }
    if (i < HC) g_cb2[i] = 0.f;
}

// ---------------- CSR build (by dst) ----------------
__global__ void k_hist(const int* __restrict__ dst) {
    int i = blockIdx.x*256 + threadIdx.x;
    if (i < EE) atomicAdd(&g_cursor[dst[i]], 1);
}

__global__ void k_scan() {
    __shared__ int sS[1024];
    int t = threadIdx.x;
    const int CH = 49;
    int b0 = t*CH;
    int sum = 0;
    for (int i = 0; i < CH; i++) { int idx = b0+i; if (idx < NN) sum += g_cursor[idx]; }
    sS[t] = sum; __syncthreads();
    for (int off = 1; off < 1024; off <<= 1) {
        int v = (t >= off) ? sS[t-off] : 0;
        __syncthreads();
        sS[t] += v;
        __syncthreads();
    }
    int run = sS[t] - sum;
    for (int i = 0; i < CH; i++) {
        int idx = b0+i;
        if (idx < NN) {
            int dg = g_cursor[idx];
            g_rowptr[idx] = run;
            g_cursor[idx] = run;
            run += dg;
        }
    }
    if (t == 1023) g_rowptr[NN] = sS[1023];
}

__global__ void k_scatter(const int* __restrict__ src, const int* __restrict__ dst) {
    int i = blockIdx.x*256 + threadIdx.x;
    if (i < EE) {
        int p = atomicAdd(&g_cursor[dst[i]], 1);
        g_csr[p] = src[i];
    }
}

// ---------------- transform v3: dup-a in dynamic smem, f32x2, fused attn ----
// dyn smem layout (floats): sIn2[2][16*256] (dup pairs), sW[2][16*132]
#define T3_DYN_BYTES ((2*16*256 + 2*16*132)*4)
__global__ void __launch_bounds__(256) k_transform3(
        const float* __restrict__ in_ptr, int useGOut,
        const float* __restrict__ W, int Fin,
        const float* __restrict__ asv, const float* __restrict__ adv) {
    extern __shared__ float dyn[];
    float* sIn2 = dyn;                    // 2 * 4096 floats
    float* sWb  = dyn + 2*16*256;         // 2 * 2112 floats
    __shared__ float sAs[512], sAd[512];
    const float* in = useGOut ? (const float*)g_out : in_ptr;
    int tid = threadIdx.x;
    int n0 = blockIdx.x*128;
    int tx = tid & 15, ty = tid >> 4;

    for (int i = tid; i < 512; i += 256) { sAs[i] = 0.f; sAd[i] = 0.f; }

    ull acc2[8][4];
#pragma unroll
    for (int r = 0; r < 8; r++)
#pragma unroll
        for (int c = 0; c < 4; c++) acc2[r][c] = 0ULL;

    int nCh = (Fin + 15) >> 4;
    {
#pragma unroll
        for (int i = 0; i < 8; i++) {
            int idx = tid + i*256;
            int row = idx >> 4, f = idx & 15;
            int n = n0 + row;
            float v = 0.f;
            if (n < NN && f < Fin) v = in[n*Fin + f];
            *(float2*)&sIn2[f*256 + row*2] = make_float2(v, v);
        }
#pragma unroll
        for (int i = 0; i < 8; i++) {
            int idx = tid + i*256;
            int col = idx & 127, f = idx >> 7;
            sWb[f*132 + col] = (f < Fin) ? W[f*HC + col] : 0.f;
        }
    }
    __syncthreads();

    float pI[8], pW8[8];
    for (int ch = 0; ch < nCh; ch++) {
        int cur = ch & 1;
        if (ch + 1 < nCh) {
            int f0 = (ch+1)*16;
#pragma unroll
            for (int i = 0; i < 8; i++) {
                int idx = tid + i*256;
                int row = idx >> 4, f = idx & 15;
                int n = n0 + row;
                pI[i] = (n < NN && f0+f < Fin) ? in[n*Fin + f0 + f] : 0.f;
            }
#pragma unroll
            for (int i = 0; i < 8; i++) {
                int idx = tid + i*256;
                int col = idx & 127, f = idx >> 7;
                pW8[i] = (f0+f < Fin) ? W[(f0+f)*HC + col] : 0.f;
            }
        }
        const float* bI = sIn2 + cur*16*256;
        const float* bW = sWb  + cur*16*132;
#pragma unroll 4
        for (int f = 0; f < 16; f++) {
            union { float4 v; ull u[2]; } w0u, w1u;
            w0u.v = *(const float4*)&bW[f*132 + tx*8];
            w1u.v = *(const float4*)&bW[f*132 + tx*8 + 4];
            ull av2[8];
#pragma unroll
            for (int r = 0; r < 8; r++)
                av2[r] = *(const ull*)&bI[f*256 + (ty*8 + r)*2];
#pragma unroll
            for (int r = 0; r < 8; r++) {
                fma2(acc2[r][0], av2[r], w0u.u[0]);
                fma2(acc2[r][1], av2[r], w0u.u[1]);
                fma2(acc2[r][2], av2[r], w1u.u[0]);
                fma2(acc2[r][3], av2[r], w1u.u[1]);
            }
        }
        if (ch + 1 < nCh) {
            __syncthreads();
            int nb = cur ^ 1;
            float* nI = sIn2 + nb*16*256;
            float* nW = sWb  + nb*16*132;
#pragma unroll
            for (int i = 0; i < 8; i++) {
                int idx = tid + i*256;
                int row = idx >> 4, f = idx & 15;
                *(float2*)&nI[f*256 + row*2] = make_float2(pI[i], pI[i]);
            }
#pragma unroll
            for (int i = 0; i < 8; i++) {
                int idx = tid + i*256;
                int col = idx & 127, f = idx >> 7;
                nW[f*132 + col] = pW8[i];
            }
            __syncthreads();
        }
    }

    // epilogue: attention dots fp32, h stored fp16
    float av8[8], bv8[8];
#pragma unroll
    for (int c = 0; c < 8; c++) { av8[c] = asv[tx*8 + c]; bv8[c] = adv[tx*8 + c]; }
    int head = tx >> 2;
#pragma unroll
    for (int r = 0; r < 8; r++) {
        float acc[8];
#pragma unroll
        for (int c = 0; c < 4; c++) {
            float2 p = unpack2(acc2[r][c]);
            acc[2*c] = p.x; acc[2*c+1] = p.y;
        }
        float ps = 0.f, pd = 0.f;
#pragma unroll
        for (int c = 0; c < 8; c++) { ps += acc[c]*av8[c]; pd += acc[c]*bv8[c]; }
        atomicAdd(&sAs[(ty*8 + r)*4 + head], ps);
        atomicAdd(&sAd[(ty*8 + r)*4 + head], pd);
        int n = n0 + ty*8 + r;
        if (n < NN) {
            union { uint4 u; __half2 h[4]; } o;
            o.h[0] = __floats2half2_rn(acc[0], acc[1]);
            o.h[1] = __floats2half2_rn(acc[2], acc[3]);
            o.h[2] = __floats2half2_rn(acc[4], acc[5]);
            o.h[3] = __floats2half2_rn(acc[6], acc[7]);
            *(uint4*)&g_hh[n*HC + tx*8] = o.u;
        }
    }
    __syncthreads();
    for (int i = tid; i < 512; i += 256) {
        int n = n0 + (i >> 2);
        if (n < NN) {
            g_asrc[n*4 + (i & 3)] = sAs[i];
            g_adst[n*4 + (i & 3)] = sAd[i];
        }
    }
}

__device__ __forceinline__ float lrelu02(float v) { return v > 0.f ? v : 0.2f*v; }

// ---------------- single-pass softmax + aggregate (fp16 h gather) ------------
__global__ void k_aggregate(const float* __restrict__ bias, int isLast,
                            const int* __restrict__ batch) {
    __shared__ int    sSrc[8][32];
    __shared__ float4 sP[8][32];
    int w = threadIdx.x >> 5, lane = threadIdx.x & 31;
    int d = blockIdx.x*8 + w;
    if (d >= NN) return;
    int r0 = g_rowptr[d], r1 = g_rowptr[d+1];
    int M = r1 - r0 + 1;
    float4 adst = *(const float4*)&g_adst[d*4];

    float4 dsum = make_float4(0.f, 0.f, 0.f, 0.f);
    float4 acc  = make_float4(0.f, 0.f, 0.f, 0.f);
    int head = lane >> 3;
    for (int cb = 0; cb < M; cb += 32) {
        int i = cb + lane;
        float4 p = make_float4(0.f, 0.f, 0.f, 0.f);
        int s = 0;
        if (i < M) {
            s = (i == 0) ? d : g_csr[r0 + i - 1];
            float4 a = *(const float4*)&g_asrc[s*4];
            p.x = __expf(lrelu02(a.x + adst.x));
            p.y = __expf(lrelu02(a.y + adst.y));
            p.z = __expf(lrelu02(a.z + adst.z));
            p.w = __expf(lrelu02(a.w + adst.w));
            dsum.x += p.x; dsum.y += p.y; dsum.z += p.z; dsum.w += p.w;
        }
        sSrc[w][lane] = s; sP[w][lane] = p;
        __syncwarp();
        int cnt = M - cb; if (cnt > 32) cnt = 32;
        for (int j = 0; j < cnt; j++) {
            int sj = sSrc[w][j];
            float4 pj = sP[w][j];
            float pk = (head == 0) ? pj.x : (head == 1) ? pj.y : (head == 2) ? pj.z : pj.w;
            uint2 hv = *(const uint2*)&g_hh[sj*HC + 4*lane];
            float2 f01 = __half22float2(*reinterpret_cast<__half2*>(&hv.x));
            float2 f23 = __half22float2(*reinterpret_cast<__half2*>(&hv.y));
            acc.x += pk*f01.x; acc.y += pk*f01.y;
            acc.z += pk*f23.x; acc.w += pk*f23.y;
        }
        __syncwarp();
    }
#pragma unroll
    for (int off = 16; off > 0; off >>= 1) {
        dsum.x += __shfl_xor_sync(0xffffffffu, dsum.x, off);
        dsum.y += __shfl_xor_sync(0xffffffffu, dsum.y, off);
        dsum.z += __shfl_xor_sync(0xffffffffu, dsum.z, off);
        dsum.w += __shfl_xor_sync(0xffffffffu, dsum.w, off);
    }
    float den = ((head == 0) ? dsum.x : (head == 1) ? dsum.y : (head == 2) ? dsum.z : dsum.w) + 1e-16f;
    float inv = 1.f/den;
    float4 bv = *(const float4*)&bias[4*lane];
    float4 o;
    o.x = fmaxf(acc.x*inv + bv.x, 0.f);
    o.y = fmaxf(acc.y*inv + bv.y, 0.f);
    o.z = fmaxf(acc.z*inv + bv.z, 0.f);
    o.w = fmaxf(acc.w*inv + bv.w, 0.f);
    if (isLast) {
        float* pp = &g_pooled[batch[d]*HC + 4*lane];
        atomicAdd(pp+0, o.x); atomicAdd(pp+1, o.y);
        atomicAdd(pp+2, o.z); atomicAdd(pp+3, o.w);
    } else {
        *(float4*)&g_out[d*HC + 4*lane] = o;
    }
}

// ---------------- conv path ----------------
__global__ void k_wsum(const float* __restrict__ emb, const float* __restrict__ cw) {
    int v = blockIdx.x;
    int t = threadIdx.x;
    if (t >= CC*KK) return;
    int o = t >> 3, k = t & 7;
    float acc = 0.f;
    for (int i = 0; i < EDIM; i++) acc += emb[v*EDIM + i]*cw[(o*EDIM + i)*KK + k];
    g_wsum[(v*KK + k)*CC + o] = acc;
}

__global__ void k_cb2(const float* __restrict__ cb, const float* __restrict__ Wx) {
    int j = threadIdx.x;
    int r0 = blockIdx.x*128;
    float local = 0.f;
    for (int r = r0; r < r0+128 && r < XTF; r++)
        local += cb[r/LOUTD]*Wx[r*HC + j];
    atomicAdd(&g_cb2[j], local);
}

// ---------------- bbuild v4: dup-ws in dynamic smem, f32x2, fp16 out --------
// dyn layout (floats): ws2[2*VOC*KK*CC] dup pairs, sWx[CC*HC]
#define B4_DYN_BYTES ((2*VOC*KK*CC + CC*HC)*4)
__global__ void __launch_bounds__(128) k_bbuild4(const float* __restrict__ Wx) {
    extern __shared__ float dyn[];
    float* ws2 = dyn;                    // 13312 floats
    float* sWx = dyn + 2*VOC*KK*CC;      // 4096 floats
    int tau = blockIdx.x;
    int tid = threadIdx.x;
    int jq = tid & 31;
    int vg = tid >> 5;
    const int vbase = (vg == 0) ? 0 : (vg == 1) ? 7 : (vg == 2) ? 14 : 20;
    const int vcnt  = (vg < 2) ? 7 : 6;
    for (int i = tid; i < VOC*KK*CC; i += 128) {
        float v = g_wsum[i];
        *(float2*)&ws2[i*2] = make_float2(v, v);
    }

    ull acc2[7][2];
#pragma unroll
    for (int vi = 0; vi < 7; vi++) { acc2[vi][0] = 0ULL; acc2[vi][1] = 0ULL; }

    int t0 = tau - 7; if (t0 < 0) t0 = 0;
    int t1 = tau;     if (t1 > LOUTD-1) t1 = LOUTD-1;

    float4 pr[8];
#pragma unroll
    for (int n = 0; n < 8; n++) {
        int i = tid*4 + n*512;
        pr[n] = *(const float4*)&Wx[((i >> 7)*LOUTD + t0)*HC + (i & 127)];
    }

    for (int t = t0; t <= t1; t++) {
        __syncthreads();
#pragma unroll
        for (int n = 0; n < 8; n++) {
            int i = tid*4 + n*512;
            *(float4*)&sWx[i] = pr[n];
        }
        __syncthreads();
        if (t < t1) {
#pragma unroll
            for (int n = 0; n < 8; n++) {
                int i = tid*4 + n*512;
                pr[n] = *(const float4*)&Wx[((i >> 7)*LOUTD + t + 1)*HC + (i & 127)];
            }
        }
        int k = tau - t;
        const float* wk2 = &ws2[2*k*CC];
#pragma unroll 4
        for (int o = 0; o < CC; o++) {
            union { float4 v; ull u[2]; } wv;
            wv.v = *(const float4*)&sWx[o*HC + jq*4];
#pragma unroll
            for (int vi = 0; vi < 7; vi++) {
                if (vi < vcnt) {
                    ull sd = *(const ull*)&wk2[2*((vbase + vi)*KK*CC + o)];
                    fma2(acc2[vi][0], sd, wv.u[0]);
                    fma2(acc2[vi][1], sd, wv.u[1]);
                }
            }
        }
    }
    for (int vi = 0; vi < vcnt; vi++) {
        float2 p0 = unpack2(acc2[vi][0]);
        float2 p1 = unpack2(acc2[vi][1]);
        union { uint2 u; __half2 h[2]; } o;
        o.h[0] = __floats2half2_rn(p0.x, p0.y);
        o.h[1] = __floats2half2_rn(p1.x, p1.y);
        *(uint2*)&g_Bh[((vbase + vi)*LL + tau)*HC + jq*4] = o.u;
    }
}

__global__ void k_applyB(const int* __restrict__ tgt) {
    int g = blockIdx.x, ch = blockIdx.y, j = threadIdx.x;
    float acc = 0.f;
    int t0 = ch*125;
#pragma unroll 5
    for (int tau = t0; tau < t0+125; tau++) {
        int v = __ldg(&tgt[g*LL + tau]);
        acc += __half2float(g_Bh[(v*LL + tau)*HC + j]);
    }
    atomicAdd(&g_xtpre[g*HC + j], acc);
}

__global__ void k_xtfin(const float* __restrict__ xb) {
    int g = blockIdx.x, j = threadIdx.x;
    float v = g_xtpre[g*HC + j] + xb[j] + g_cb2[j];
    g_xc[g*256 + 128 + j] = v > 0.f ? v : 0.f;
}

// ---------------- small dense layers ----------------
__global__ void __launch_bounds__(128) k_fc2(int Asel, int lda,
                     const float* __restrict__ W, const float* __restrict__ b,
                     int Csel, int ldc, int K, int Nout, int doRelu) {
    __shared__ float sA[8*1024];
    const float* A = (Asel == 0) ? g_pooled : (Asel == 1) ? g_xc : g_h1;
    float* C = (Csel == 0) ? g_xc : (Csel == 1) ? g_h1 : g_h2;
    int g0 = blockIdx.x*8;
    for (int i = threadIdx.x; i < 8*K; i += 128) {
        int g8 = i / K, k = i - g8*K;
        sA[g8*K + k] = A[(g0+g8)*lda + k];
    }
    __syncthreads();
    int n = blockIdx.y*128 + threadIdx.x;
    if (n >= Nout) return;
    float acc[8];
#pragma unroll
    for (int g8 = 0; g8 < 8; g8++) acc[g8] = 0.f;
#pragma unroll 2
    for (int k = 0; k < K; k++) {
        float w = W[k*Nout + n];
#pragma unroll
        for (int g8 = 0; g8 < 8; g8++) acc[g8] += sA[g8*K + k]*w;
    }
    float bv = b[n];
#pragma unroll
    for (int g8 = 0; g8 < 8; g8++) {
        float v = acc[g8] + bv;
        if (doRelu && v < 0.f) v = 0.f;
        C[(g0+g8)*ldc + n] = v;
    }
}

__global__ void k_out(const float* __restrict__ ow, const float* __restrict__ ob,
                      float* __restrict__ outp) {
    int g = blockIdx.x, lane = threadIdx.x;
    float s = 0.f;
    for (int k = lane; k < 256; k += 32) s += g_h2[g*256 + k]*ow[k];
#pragma unroll
    for (int off = 16; off > 0; off >>= 1) s += __shfl_xor_sync(0xffffffffu, s, off);
    if (lane == 0) outp[g] = s + ob[0];
}

// ---------------- host (single stream) ----------------
extern "C" void kernel_launch(void* const* d_in, const int* in_sizes, int n_in,
                              void* d_out, int out_size) {
    (void)in_sizes; (void)n_in; (void)out_size;
    const float* x       = (const float*)d_in[0];
    const int*   ei      = (const int*)  d_in[1];
    const int*   batch   = (const int*)  d_in[2];
    const int*   target  = (const int*)  d_in[3];
    const float* W1      = (const float*)d_in[4];
    const float* as1     = (const float*)d_in[5];
    const float* ad1     = (const float*)d_in[6];
    const float* b1      = (const float*)d_in[7];
    const float* Ws      = (const float*)d_in[8];
    const float* ass     = (const float*)d_in[9];
    const float* ads     = (const float*)d_in[10];
    const float* bs      = (const float*)d_in[11];
    const float* fcxd_w  = (const float*)d_in[12];
    const float* fcxd_b  = (const float*)d_in[13];
    const float* emb     = (const float*)d_in[14];
    const float* conv_w  = (const float*)d_in[15];
    const float* conv_b  = (const float*)d_in[16];
    const float* fcxt_w  = (const float*)d_in[17];
    const float* fcxt_b  = (const float*)d_in[18];
    const float* fc1_w   = (const float*)d_in[19];
    const float* fc1_b   = (const float*)d_in[20];
    const float* fc2_w   = (const float*)d_in[21];
    const float* fc2_b   = (const float*)d_in[22];
    const float* out_w   = (const float*)d_in[23];
    const float* out_b   = (const float*)d_in[24];
    const int* esrc = ei;
    const int* edst = ei + EE;

    // opt-in dynamic smem (host attribute calls; not allocations)
    cudaFuncSetAttribute(k_transform3, cudaFuncAttributeMaxDynamicSharedMemorySize, T3_DYN_BYTES);
    cudaFuncSetAttribute(k_bbuild4,    cudaFuncAttributeMaxDynamicSharedMemorySize, B4_DYN_BYTES);

    k_zero<<<(NN+255)/256, 256>>>();                              // 0
    k_wsum<<<VOC, 256>>>(emb, conv_w);                            // 1
    k_hist<<<(EE+255)/256, 256>>>(edst);                          // 2
    k_transform3<<<(NN+127)/128, 256, T3_DYN_BYTES>>>(x, 0, W1, FDIM, as1, ad1);  // 3 (profiled)
    k_bbuild4<<<LL, 128, B4_DYN_BYTES>>>(fcxt_w);                 // 4
    k_scan<<<1, 1024>>>();                                        // 5
    k_scatter<<<(EE+255)/256, 256>>>(esrc, edst);                 // 6
    k_cb2<<<(XTF+127)/128, 128>>>(conv_b, fcxt_w);
    k_applyB<<<dim3(GG,8), 128>>>(target);
    k_xtfin<<<GG, 128>>>(fcxt_b);

    // GAT layers
    k_aggregate<<<(NN+7)/8, 256>>>(b1, 0, batch);
    for (int l = 0; l < 4; l++) {
        k_transform3<<<(NN+127)/128, 256, T3_DYN_BYTES>>>(nullptr, 1, Ws + l*HC*HC, HC,
                                                          ass + l*HH*CC, ads + l*HH*CC);
        k_aggregate<<<(NN+7)/8, 256>>>(bs + l*HC, l == 3, batch);
    }

    // xd (writes g_xc[:, :128])
    k_fc2<<<dim3(GG/8,1), 128>>>(0, HC, fcxd_w, fcxd_b, 0, 256, HC, HC, 1);

    // MLP head
    k_fc2<<<dim3(GG/8,8), 128>>>(1, 256,  fc1_w, fc1_b, 1, 1024, 256,  1024, 1);
    k_fc2<<<dim3(GG/8,2), 128>>>(2, 1024, fc2_w, fc2_b, 2, 256,  1024, 256,  1);
    k_out<<<GG, 32>>>(out_w, out_b, (float*)d_out);
}

// round 9
// speedup vs baseline: 1.2589x; 1.2589x over previous
#include <cuda_runtime.h>
#include <cuda_bf16.h>
#include <cuda_fp16.h>
#include <math.h>

#define NN 50000
#define EE 800000
#define GG 256
#define LL 1000
#define HH 4
#define CC 32
#define FDIM 78
#define EDIM 128
#define VOC 26
#define KK 8
#define LOUTD 993
#define HC 128
#define XTF (CC*LOUTD)

typedef unsigned long long ull;
typedef unsigned int uint32;

__device__ __forceinline__ ull pack2(float x, float y) {
    ull r; asm("mov.b64 %0, {%1, %2};" : "=l"(r) : "f"(x), "f"(y)); return r;
}
__device__ __forceinline__ void fma2(ull& acc, ull a, ull b) {
    asm("fma.rn.f32x2 %0, %1, %2, %0;" : "+l"(acc) : "l"(a), "l"(b));
}
__device__ __forceinline__ float2 unpack2(ull v) {
    float2 f; asm("mov.b64 {%0, %1}, %2;" : "=f"(f.x), "=f"(f.y) : "l"(v)); return f;
}
__device__ __forceinline__ void mma16816(float* c, const uint32* a, uint32 b0, uint32 b1) {
    asm volatile("mma.sync.aligned.m16n8k16.row.col.f32.f16.f16.f32 "
        "{%0,%1,%2,%3}, {%4,%5,%6,%7}, {%8,%9}, {%0,%1,%2,%3};"
        : "+f"(c[0]), "+f"(c[1]), "+f"(c[2]), "+f"(c[3])
        : "r"(a[0]), "r"(a[1]), "r"(a[2]), "r"(a[3]), "r"(b0), "r"(b1));
}

// ---------------- scratch ----------------
__device__ __align__(128) __half g_hh[NN*HC];    // fp16 h for gathers
__device__ __align__(128) float g_out[NN*HC];    // fp32 layer output (transform input)
__device__ __align__(16)  float g_asrc[NN*4];
__device__ __align__(16)  float g_adst[NN*4];
__device__ int   g_rowptr[NN+1];
__device__ int   g_cursor[NN];
__device__ int   g_csr[EE];
__device__ __align__(128) __half g_Bh[VOC*LL*HC];  // fp16 token->xt table
__device__ float g_wsum[VOC*KK*CC];
__device__ float g_cb2[HC];
__device__ __align__(16) float g_pooled[GG*HC];
__device__ float g_xtpre[GG*HC];
__device__ float g_xc[GG*256];
__device__ float g_h1[GG*1024];
__device__ float g_h2[GG*256];

// ---------------- init ----------------
__global__ void k_zero() {
    int i = blockIdx.x*256 + threadIdx.x;
    if (i < NN) g_cursor[i] = 0;
    if (i < GG*HC) { g_pooled[i] = 0.f; g_xtpre[i] = 0.f; }
    if (i < HC) g_cb2[i] = 0.f;
}

// ---------------- CSR build (by dst) ----------------
__global__ void k_hist(const int* __restrict__ dst) {
    int i = blockIdx.x*256 + threadIdx.x;
    if (i < EE) atomicAdd(&g_cursor[dst[i]], 1);
}

__global__ void k_scan() {
    __shared__ int sS[1024];
    int t = threadIdx.x;
    const int CH = 49;
    int b0 = t*CH;
    int sum = 0;
    for (int i = 0; i < CH; i++) { int idx = b0+i; if (idx < NN) sum += g_cursor[idx]; }
    sS[t] = sum; __syncthreads();
    for (int off = 1; off < 1024; off <<= 1) {
        int v = (t >= off) ? sS[t-off] : 0;
        __syncthreads();
        sS[t] += v;
        __syncthreads();
    }
    int run = sS[t] - sum;
    for (int i = 0; i < CH; i++) {
        int idx = b0+i;
        if (idx < NN) {
            int dg = g_cursor[idx];
            g_rowptr[idx] = run;
            g_cursor[idx] = run;
            run += dg;
        }
    }
    if (t == 1023) g_rowptr[NN] = sS[1023];
}

__global__ void k_scatter(const int* __restrict__ src, const int* __restrict__ dst) {
    int i = blockIdx.x*256 + threadIdx.x;
    if (i < EE) {
        int p = atomicAdd(&g_cursor[dst[i]], 1);
        g_csr[p] = src[i];
    }
}

// ---------------- transform v4: fp16 HMMA (mma.sync m16n8k16), fused attn ----
// 128x128 block tile, 8 warps as 4(row)x2(col), warp tile 32x64.
// A,B staged per 32-K chunk in smem, stride 40 halves (conflict-free frags).
__global__ void __launch_bounds__(256) k_transform4(
        const float* __restrict__ in_ptr, int useGOut,
        const float* __restrict__ W, int Fin,
        const float* __restrict__ asv, const float* __restrict__ adv) {
    __shared__ __half A_s[128*40];
    __shared__ __half B_s[128*40];
    __shared__ float sAs[512], sAd[512];
    __shared__ float sAv[128], sDv[128];
    const float* in = useGOut ? (const float*)g_out : in_ptr;
    int tid = threadIdx.x;
    int n0 = blockIdx.x*128;
    int warp = tid >> 5, lane = tid & 31;
    int wr = warp & 3;          // row group: rows wr*32 .. wr*32+31
    int wc = warp >> 2;         // col group: cols wc*64 .. wc*64+63
    int lr = lane >> 2;         // 0..7
    int hk = lane & 3;          // 0..3

    for (int i = tid; i < 512; i += 256) { sAs[i] = 0.f; sAd[i] = 0.f; }
    if (tid < 128) { sAv[tid] = asv[tid]; sDv[tid] = adv[tid]; }

    float c[2][8][4];
#pragma unroll
    for (int mi = 0; mi < 2; mi++)
#pragma unroll
        for (int ni = 0; ni < 8; ni++)
#pragma unroll
            for (int q = 0; q < 4; q++) c[mi][ni][q] = 0.f;

    int nCh = (Fin + 31) >> 5;
    for (int ci = 0; ci < nCh; ci++) {
        int f0 = ci*32;
        __syncthreads();
        // stage A: 128 rows x 32 k (fp32 -> fp16)
        for (int p = tid; p < 2048; p += 256) {
            int row = p >> 4, kp = p & 15, k = 2*kp;
            int n = n0 + row, f = f0 + k;
            float v0 = 0.f, v1 = 0.f;
            if (n < NN && f < Fin)     v0 = in[n*Fin + f];
            if (n < NN && f + 1 < Fin) v1 = in[n*Fin + f + 1];
            *(__half2*)&A_s[row*40 + k] = __floats2half2_rn(v0, v1);
        }
        // stage B: W[k][col] -> B_s[col][k] (transposed, fp16)
        for (int p = tid; p < 2048; p += 256) {
            int col = p & 127, kp = p >> 7, k = 2*kp;
            int f = f0 + k;
            float w0 = (f < Fin)     ? W[f*HC + col]       : 0.f;
            float w1 = (f + 1 < Fin) ? W[(f + 1)*HC + col] : 0.f;
            *(__half2*)&B_s[col*40 + k] = __floats2half2_rn(w0, w1);
        }
        __syncthreads();
#pragma unroll
        for (int kk = 0; kk < 32; kk += 16) {
            uint32 a[2][4];
#pragma unroll
            for (int mi = 0; mi < 2; mi++) {
                int r = wr*32 + mi*16 + lr;
                int base = r*40 + kk + 2*hk;
                a[mi][0] = *(const uint32*)&A_s[base];
                a[mi][1] = *(const uint32*)&A_s[base + 8*40];
                a[mi][2] = *(const uint32*)&A_s[base + 8];
                a[mi][3] = *(const uint32*)&A_s[base + 8*40 + 8];
            }
#pragma unroll
            for (int ni = 0; ni < 8; ni++) {
                int cb = wc*64 + ni*8 + lr;
                int bbase = cb*40 + kk + 2*hk;
                uint32 b0 = *(const uint32*)&B_s[bbase];
                uint32 b1 = *(const uint32*)&B_s[bbase + 8];
                mma16816(c[0][ni], a[0], b0, b1);
                mma16816(c[1][ni], a[1], b0, b1);
            }
        }
    }
    __syncthreads();

    // epilogue: attention dots (fp32 accum) + fp16 h store
    int lc2 = 2*hk;
#pragma unroll
    for (int mi = 0; mi < 2; mi++) {
        int r0l = wr*32 + mi*16 + lr;      // local row (first half)
        int r1l = r0l + 8;
        float ps[2][2] = {{0.f,0.f},{0.f,0.f}};   // [rowhalf][headlocal]
        float pd[2][2] = {{0.f,0.f},{0.f,0.f}};
#pragma unroll
        for (int ni = 0; ni < 8; ni++) {
            int colb = wc*64 + ni*8 + lc2;
            int hl = ni >> 2;
            float av0 = sAv[colb], av1 = sAv[colb+1];
            float dv0 = sDv[colb], dv1 = sDv[colb+1];
            float c0 = c[mi][ni][0], c1 = c[mi][ni][1];
            float c2v = c[mi][ni][2], c3v = c[mi][ni][3];
            ps[0][hl] += c0*av0 + c1*av1;  pd[0][hl] += c0*dv0 + c1*dv1;
            ps[1][hl] += c2v*av0 + c3v*av1; pd[1][hl] += c2v*dv0 + c3v*dv1;
            int n0g = n0 + r0l, n1g = n0 + r1l;
            if (n0g < NN) *(__half2*)&g_hh[n0g*HC + colb] = __floats2half2_rn(c0, c1);
            if (n1g < NN) *(__half2*)&g_hh[n1g*HC + colb] = __floats2half2_rn(c2v, c3v);
        }
        int hb = wc*2;
        atomicAdd(&sAs[r0l*4 + hb + 0], ps[0][0]);
        atomicAdd(&sAs[r0l*4 + hb + 1], ps[0][1]);
        atomicAdd(&sAs[r1l*4 + hb + 0], ps[1][0]);
        atomicAdd(&sAs[r1l*4 + hb + 1], ps[1][1]);
        atomicAdd(&sAd[r0l*4 + hb + 0], pd[0][0]);
        atomicAdd(&sAd[r0l*4 + hb + 1], pd[0][1]);
        atomicAdd(&sAd[r1l*4 + hb + 0], pd[1][0]);
        atomicAdd(&sAd[r1l*4 + hb + 1], pd[1][1]);
    }
    __syncthreads();
    for (int i = tid; i < 512; i += 256) {
        int n = n0 + (i >> 2);
        if (n < NN) {
            g_asrc[n*4 + (i & 3)] = sAs[i];
            g_adst[n*4 + (i & 3)] = sAd[i];
        }
    }
}

__device__ __forceinline__ float lrelu02(float v) { return v > 0.f ? v : 0.2f*v; }

// ---------------- single-pass softmax + aggregate (fp16 h gather) ------------
__global__ void k_aggregate(const float* __restrict__ bias, int isLast,
                            const int* __restrict__ batch) {
    __shared__ int    sSrc[8][32];
    __shared__ float4 sP[8][32];
    int w = threadIdx.x >> 5, lane = threadIdx.x & 31;
    int d = blockIdx.x*8 + w;
    if (d >= NN) return;
    int r0 = g_rowptr[d], r1 = g_rowptr[d+1];
    int M = r1 - r0 + 1;
    float4 adst = *(const float4*)&g_adst[d*4];

    float4 dsum = make_float4(0.f, 0.f, 0.f, 0.f);
    float4 acc  = make_float4(0.f, 0.f, 0.f, 0.f);
    int head = lane >> 3;
    for (int cb = 0; cb < M; cb += 32) {
        int i = cb + lane;
        float4 p = make_float4(0.f, 0.f, 0.f, 0.f);
        int s = 0;
        if (i < M) {
            s = (i == 0) ? d : g_csr[r0 + i - 1];
            float4 a = *(const float4*)&g_asrc[s*4];
            p.x = __expf(lrelu02(a.x + adst.x));
            p.y = __expf(lrelu02(a.y + adst.y));
            p.z = __expf(lrelu02(a.z + adst.z));
            p.w = __expf(lrelu02(a.w + adst.w));
            dsum.x += p.x; dsum.y += p.y; dsum.z += p.z; dsum.w += p.w;
        }
        sSrc[w][lane] = s; sP[w][lane] = p;
        __syncwarp();
        int cnt = M - cb; if (cnt > 32) cnt = 32;
        for (int j = 0; j < cnt; j++) {
            int sj = sSrc[w][j];
            float4 pj = sP[w][j];
            float pk = (head == 0) ? pj.x : (head == 1) ? pj.y : (head == 2) ? pj.z : pj.w;
            uint2 hv = *(const uint2*)&g_hh[sj*HC + 4*lane];
            float2 f01 = __half22float2(*reinterpret_cast<__half2*>(&hv.x));
            float2 f23 = __half22float2(*reinterpret_cast<__half2*>(&hv.y));
            acc.x += pk*f01.x; acc.y += pk*f01.y;
            acc.z += pk*f23.x; acc.w += pk*f23.y;
        }
        __syncwarp();
    }
#pragma unroll
    for (int off = 16; off > 0; off >>= 1) {
        dsum.x += __shfl_xor_sync(0xffffffffu, dsum.x, off);
        dsum.y += __shfl_xor_sync(0xffffffffu, dsum.y, off);
        dsum.z += __shfl_xor_sync(0xffffffffu, dsum.z, off);
        dsum.w += __shfl_xor_sync(0xffffffffu, dsum.w, off);
    }
    float den = ((head == 0) ? dsum.x : (head == 1) ? dsum.y : (head == 2) ? dsum.z : dsum.w) + 1e-16f;
    float inv = 1.f/den;
    float4 bv = *(const float4*)&bias[4*lane];
    float4 o;
    o.x = fmaxf(acc.x*inv + bv.x, 0.f);
    o.y = fmaxf(acc.y*inv + bv.y, 0.f);
    o.z = fmaxf(acc.z*inv + bv.z, 0.f);
    o.w = fmaxf(acc.w*inv + bv.w, 0.f);
    if (isLast) {
        float* pp = &g_pooled[batch[d]*HC + 4*lane];
        atomicAdd(pp+0, o.x); atomicAdd(pp+1, o.y);
        atomicAdd(pp+2, o.z); atomicAdd(pp+3, o.w);
    } else {
        *(float4*)&g_out[d*HC + 4*lane] = o;
    }
}

// ---------------- conv path ----------------
__global__ void k_wsum(const float* __restrict__ emb, const float* __restrict__ cw) {
    int v = blockIdx.x;
    int t = threadIdx.x;
    if (t >= CC*KK) return;
    int o = t >> 3, k = t & 7;
    float acc = 0.f;
    for (int i = 0; i < EDIM; i++) acc += emb[v*EDIM + i]*cw[(o*EDIM + i)*KK + k];
    g_wsum[(v*KK + k)*CC + o] = acc;
}

__global__ void k_cb2(const float* __restrict__ cb, const float* __restrict__ Wx) {
    int j = threadIdx.x;
    int r0 = blockIdx.x*128;
    float local = 0.f;
    for (int r = r0; r < r0+128 && r < XTF; r++)
        local += cb[r/LOUTD]*Wx[r*HC + j];
    atomicAdd(&g_cb2[j], local);
}

// block per tau; single slab + register prefetch; f32x2 inner; fp16 out. 42KB smem.
__global__ void __launch_bounds__(128) k_bbuild3(const float* __restrict__ Wx) {
    __shared__ float ws[VOC*KK*CC];     // 26KB
    __shared__ float sWx[CC*HC];        // 16KB
    int tau = blockIdx.x;
    int tid = threadIdx.x;
    int jq = tid & 31;
    int vg = tid >> 5;
    const int vbase = (vg == 0) ? 0 : (vg == 1) ? 7 : (vg == 2) ? 14 : 20;
    const int vcnt  = (vg < 2) ? 7 : 6;
    for (int i = tid; i < VOC*KK*CC; i += 128) ws[i] = g_wsum[i];

    ull acc2[7][2];
#pragma unroll
    for (int vi = 0; vi < 7; vi++) { acc2[vi][0] = 0ULL; acc2[vi][1] = 0ULL; }

    int t0 = tau - 7; if (t0 < 0) t0 = 0;
    int t1 = tau;     if (t1 > LOUTD-1) t1 = LOUTD-1;

    float4 pr[8];
#pragma unroll
    for (int n = 0; n < 8; n++) {
        int i = tid*4 + n*512;
        pr[n] = *(const float4*)&Wx[((i >> 7)*LOUTD + t0)*HC + (i & 127)];
    }

    for (int t = t0; t <= t1; t++) {
        __syncthreads();
#pragma unroll
        for (int n = 0; n < 8; n++) {
            int i = tid*4 + n*512;
            *(float4*)&sWx[i] = pr[n];
        }
        __syncthreads();
        if (t < t1) {
#pragma unroll
            for (int n = 0; n < 8; n++) {
                int i = tid*4 + n*512;
                pr[n] = *(const float4*)&Wx[((i >> 7)*LOUTD + t + 1)*HC + (i & 127)];
            }
        }
        int k = tau - t;
        const float* wk = &ws[k*CC];
#pragma unroll 4
        for (int o = 0; o < CC; o++) {
            union { float4 v; ull u[2]; } wv;
            wv.v = *(const float4*)&sWx[o*HC + jq*4];
#pragma unroll
            for (int vi = 0; vi < 7; vi++) {
                if (vi < vcnt) {
                    float s = wk[(vbase + vi)*KK*CC + o];
                    ull sd = pack2(s, s);
                    fma2(acc2[vi][0], sd, wv.u[0]);
                    fma2(acc2[vi][1], sd, wv.u[1]);
                }
            }
        }
    }
    for (int vi = 0; vi < vcnt; vi++) {
        float2 p0 = unpack2(acc2[vi][0]);
        float2 p1 = unpack2(acc2[vi][1]);
        union { uint2 u; __half2 h[2]; } o;
        o.h[0] = __floats2half2_rn(p0.x, p0.y);
        o.h[1] = __floats2half2_rn(p1.x, p1.y);
        *(uint2*)&g_Bh[((vbase + vi)*LL + tau)*HC + jq*4] = o.u;
    }
}

__global__ void k_applyB(const int* __restrict__ tgt) {
    int g = blockIdx.x, ch = blockIdx.y, j = threadIdx.x;
    float acc = 0.f;
    int t0 = ch*125;
#pragma unroll 5
    for (int tau = t0; tau < t0+125; tau++) {
        int v = __ldg(&tgt[g*LL + tau]);
        acc += __half2float(g_Bh[(v*LL + tau)*HC + j]);
    }
    atomicAdd(&g_xtpre[g*HC + j], acc);
}

__global__ void k_xtfin(const float* __restrict__ xb) {
    int g = blockIdx.x, j = threadIdx.x;
    float v = g_xtpre[g*HC + j] + xb[j] + g_cb2[j];
    g_xc[g*256 + 128 + j] = v > 0.f ? v : 0.f;
}

// ---------------- small dense layers ----------------
__global__ void __launch_bounds__(128) k_fc2(int Asel, int lda,
                     const float* __restrict__ W, const float* __restrict__ b,
                     int Csel, int ldc, int K, int Nout, int doRelu) {
    __shared__ float sA[8*1024];
    const float* A = (Asel == 0) ? g_pooled : (Asel == 1) ? g_xc : g_h1;
    float* C = (Csel == 0) ? g_xc : (Csel == 1) ? g_h1 : g_h2;
    int g0 = blockIdx.x*8;
    for (int i = threadIdx.x; i < 8*K; i += 128) {
        int g8 = i / K, k = i - g8*K;
        sA[g8*K + k] = A[(g0+g8)*lda + k];
    }
    __syncthreads();
    int n = blockIdx.y*128 + threadIdx.x;
    if (n >= Nout) return;
    float acc[8];
#pragma unroll
    for (int g8 = 0; g8 < 8; g8++) acc[g8] = 0.f;
#pragma unroll 2
    for (int k = 0; k < K; k++) {
        float w = W[k*Nout + n];
#pragma unroll
        for (int g8 = 0; g8 < 8; g8++) acc[g8] += sA[g8*K + k]*w;
    }
    float bv = b[n];
#pragma unroll
    for (int g8 = 0; g8 < 8; g8++) {
        float v = acc[g8] + bv;
        if (doRelu && v < 0.f) v = 0.f;
        C[(g0+g8)*ldc + n] = v;
    }
}

__global__ void k_out(const float* __restrict__ ow, const float* __restrict__ ob,
                      float* __restrict__ outp) {
    int g = blockIdx.x, lane = threadIdx.x;
    float s = 0.f;
    for (int k = lane; k < 256; k += 32) s += g_h2[g*256 + k]*ow[k];
#pragma unroll
    for (int off = 16; off > 0; off >>= 1) s += __shfl_xor_sync(0xffffffffu, s, off);
    if (lane == 0) outp[g] = s + ob[0];
}

// ---------------- host (single stream) ----------------
extern "C" void kernel_launch(void* const* d_in, const int* in_sizes, int n_in,
                              void* d_out, int out_size) {
    (void)in_sizes; (void)n_in; (void)out_size;
    const float* x       = (const float*)d_in[0];
    const int*   ei      = (const int*)  d_in[1];
    const int*   batch   = (const int*)  d_in[2];
    const int*   target  = (const int*)  d_in[3];
    const float* W1      = (const float*)d_in[4];
    const float* as1     = (const float*)d_in[5];
    const float* ad1     = (const float*)d_in[6];
    const float* b1      = (const float*)d_in[7];
    const float* Ws      = (const float*)d_in[8];
    const float* ass     = (const float*)d_in[9];
    const float* ads     = (const float*)d_in[10];
    const float* bs      = (const float*)d_in[11];
    const float* fcxd_w  = (const float*)d_in[12];
    const float* fcxd_b  = (const float*)d_in[13];
    const float* emb     = (const float*)d_in[14];
    const float* conv_w  = (const float*)d_in[15];
    const float* conv_b  = (const float*)d_in[16];
    const float* fcxt_w  = (const float*)d_in[17];
    const float* fcxt_b  = (const float*)d_in[18];
    const float* fc1_w   = (const float*)d_in[19];
    const float* fc1_b   = (const float*)d_in[20];
    const float* fc2_w   = (const float*)d_in[21];
    const float* fc2_b   = (const float*)d_in[22];
    const float* out_w   = (const float*)d_in[23];
    const float* out_b   = (const float*)d_in[24];
    const int* esrc = ei;
    const int* edst = ei + EE;

    k_zero<<<(NN+255)/256, 256>>>();                              // 0
    k_wsum<<<VOC, 256>>>(emb, conv_w);                            // 1
    k_hist<<<(EE+255)/256, 256>>>(edst);                          // 2
    k_transform4<<<(NN+127)/128, 256>>>(x, 0, W1, FDIM, as1, ad1);// 3 (profiled)
    k_bbuild3<<<LL, 128>>>(fcxt_w);                               // 4
    k_scan<<<1, 1024>>>();                                        // 5
    k_scatter<<<(EE+255)/256, 256>>>(esrc, edst);                 // 6
    k_cb2<<<(XTF+127)/128, 128>>>(conv_b, fcxt_w);
    k_applyB<<<dim3(GG,8), 128>>>(target);
    k_xtfin<<<GG, 128>>>(fcxt_b);

    // GAT layers
    k_aggregate<<<(NN+7)/8, 256>>>(b1, 0, batch);
    for (int l = 0; l < 4; l++) {
        k_transform4<<<(NN+127)/128, 256>>>(nullptr, 1, Ws + l*HC*HC, HC,
                                            ass + l*HH*CC, ads + l*HH*CC);
        k_aggregate<<<(NN+7)/8, 256>>>(bs + l*HC, l == 3, batch);
    }

    // xd (writes g_xc[:, :128])
    k_fc2<<<dim3(GG/8,1), 128>>>(0, HC, fcxd_w, fcxd_b, 0, 256, HC, HC, 1);

    // MLP head
    k_fc2<<<dim3(GG/8,8), 128>>>(1, 256,  fc1_w, fc1_b, 1, 1024, 256,  1024, 1);
    k_fc2<<<dim3(GG/8,2), 128>>>(2, 1024, fc2_w, fc2_b, 2, 256,  1024, 256,  1);
    k_out<<<GG, 32>>>(out_w, out_b, (float*)d_out);
}